// round 6
// baseline (speedup 1.0000x reference)
#include <cuda_runtime.h>
#include <cstdint>
#include <math_constants.h>

// Problem constants (fixed instance)
#define BSZ   16
#define DIM   4096
#define NH    32
#define NKV   8
#define HD    128
#define MSL   4096
// start_pos = 4095, seqlen = 1

// ---------------- scratch (no allocation allowed) ----------------
__device__ float g_q [BSZ * DIM];        // roped Q   [b][head*128+d]
__device__ float g_kn[BSZ * NKV * HD];   // roped new K [b][kv*128+d]
__device__ float g_vn[BSZ * NKV * HD];   // new V       [b][kv*128+d]
__device__ float g_ao[BSZ * DIM];        // attention out [b][head*128+d]

__device__ __forceinline__ void cp_async16(void* dst, const void* src) {
    uint32_t d = (uint32_t)__cvta_generic_to_shared(dst);
    asm volatile("cp.async.cg.shared.global [%0], [%1], 16;" :: "r"(d), "l"(src) : "memory");
}
__device__ __forceinline__ void cp_commit() {
    asm volatile("cp.async.commit_group;" ::: "memory");
}

// =================================================================
// Batched GEMV core: 2 rows per warp, 16 batches, K = 4096 in 4
// SMEM chunks of 1024 floats per batch ( [b][d] layout, 64 KB ).
// On return every lane holds the fully reduced a0[16], a1[16].
// =================================================================
__device__ __forceinline__ void gemv2_16b(const float4* __restrict__ x4,   // [b][1024] float4
                                          const float4* __restrict__ W0,  // row e0 as float4
                                          const float4* __restrict__ W1,  // row e0+1
                                          float4* xs4,                    // smem, 4096 float4
                                          float* a0, float* a1)
{
    const int tid  = threadIdx.x;
    const int lane = tid & 31;
#pragma unroll
    for (int b = 0; b < 16; ++b) { a0[b] = 0.f; a1[b] = 0.f; }

    for (int c = 0; c < 4; ++c) {
        __syncthreads();            // previous chunk fully consumed
#pragma unroll
        for (int k = 0; k < 16; ++k) {
            int idx = (k << 8) + tid;                  // 0..4095
            int b   = idx >> 8;
            int dl  = idx & 255;
            xs4[idx] = x4[(b << 10) + (c << 8) + dl];
        }
        __syncthreads();
        const float4* W0c = W0 + (c << 8);
        const float4* W1c = W1 + (c << 8);
#pragma unroll 2
        for (int it = 0; it < 8; ++it) {
            int d4 = lane + (it << 5);
            float4 w0 = W0c[d4];
            float4 w1 = W1c[d4];
#pragma unroll
            for (int b = 0; b < 16; ++b) {
                float4 xv = xs4[(b << 8) + d4];
                a0[b] = fmaf(w0.x, xv.x, a0[b]);
                a0[b] = fmaf(w0.y, xv.y, a0[b]);
                a0[b] = fmaf(w0.z, xv.z, a0[b]);
                a0[b] = fmaf(w0.w, xv.w, a0[b]);
                a1[b] = fmaf(w1.x, xv.x, a1[b]);
                a1[b] = fmaf(w1.y, xv.y, a1[b]);
                a1[b] = fmaf(w1.z, xv.z, a1[b]);
                a1[b] = fmaf(w1.w, xv.w, a1[b]);
            }
        }
    }
    // full butterfly reduce -> all lanes hold totals
#pragma unroll
    for (int off = 16; off; off >>= 1) {
#pragma unroll
        for (int b = 0; b < 16; ++b) {
            a0[b] += __shfl_xor_sync(0xffffffffu, a0[b], off);
            a1[b] += __shfl_xor_sync(0xffffffffu, a1[b], off);
        }
    }
}

// =================================================================
// Stage 1: Q/K/V projections + RoPE.  6144 rows total
// (q:0..4095, k:4096..5119, v:5120..6143); 16 rows / block.
// =================================================================
__global__ __launch_bounds__(256)
void qkv_kernel(const float* __restrict__ x,
                const float* __restrict__ wq,
                const float* __restrict__ wk,
                const float* __restrict__ wv,
                const float* __restrict__ fc,
                const float* __restrict__ fs)
{
    extern __shared__ float4 xs4[];
    const int warp = threadIdx.x >> 5;
    const int lane = threadIdx.x & 31;
    const int r0   = (blockIdx.x * 8 + warp) * 2;     // even row

    const float* W; int e0; int kind;
    if (r0 < 4096)      { W = wq; e0 = r0;        kind = 0; }
    else if (r0 < 5120) { W = wk; e0 = r0 - 4096; kind = 1; }
    else                { W = wv; e0 = r0 - 5120; kind = 2; }

    const float4* W0 = (const float4*)(W + (size_t)e0 * DIM);
    const float4* W1 = (const float4*)(W + (size_t)(e0 + 1) * DIM);

    float a0[16], a1[16];
    gemv2_16b((const float4*)x, W0, W1, xs4, a0, a1);

    if (lane < 16) {
        int b = lane;
        float va = a0[b], vb = a1[b];
        float o0 = va, o1 = vb;
        if (kind < 2) {   // RoPE on q and k (interleaved pairs)
            int j = e0 & 127;        // even
            int i = j >> 1;
            float cc = fc[i], ss = fs[i];
            o0 = va * cc - vb * ss;
            o1 = va * ss + vb * cc;
        }
        if (kind == 0)      { g_q [b * DIM  + e0] = o0; g_q [b * DIM  + e0 + 1] = o1; }
        else if (kind == 1) { g_kn[b * 1024 + e0] = o0; g_kn[b * 1024 + e0 + 1] = o1; }
        else                { g_vn[b * 1024 + e0] = o0; g_vn[b * 1024 + e0 + 1] = o1; }
    }
}

// =================================================================
// Stage 2: attention.  One CTA per (batch, kv_head): 128 CTAs,
// 4 Q heads per CTA.  64-key tiles, double-buffered cp.async.
// Online softmax; (m,l) replicated across the 64 threads of a head.
// =================================================================
#define TILE     64
#define NTILES   (MSL / TILE)
#define KROW_F4  33                 // padded row stride in float4 (conflict-free)
#define TILE_F4  (TILE * KROW_F4)   // 2112

__global__ __launch_bounds__(256, 1)
void attn_kernel(const float* __restrict__ cache_k,
                 const float* __restrict__ cache_v)
{
    extern __shared__ float4 sm4[];
    float4* Kbuf = sm4;                     // 2 * 2112
    float4* Vbuf = sm4 + 2 * TILE_F4;       // 2 * 2112
    float4* q4   = sm4 + 4 * TILE_F4;       // 128
    float*  p_sh = (float*)(q4 + 128);      // 256
    float*  red  = p_sh + 256;              // 8
    float*  sums = red + 8;                 // 8

    const int tid  = threadIdx.x;
    const int b    = blockIdx.x >> 3;
    const int kv   = blockIdx.x & 7;
    const int h    = tid >> 6;              // 0..3 (q head within group)
    const int t    = tid & 63;              // key slot  (score phase)
    const int j    = tid & 63;              // float2 col (PV phase)
    const int lane = tid & 31;
    const int warp = tid >> 5;

    // load this CTA's 4 q heads into smem
    if (tid < 128) {
        int hh = tid >> 5, d4 = tid & 31;
        q4[tid] = ((const float4*)g_q)[b * 1024 + (kv * 4 + hh) * 32 + d4];
    }

    const float4* Ksrc = (const float4*)cache_k + ((size_t)b * MSL * NKV + kv) * 32;
    const float4* Vsrc = (const float4*)cache_v + ((size_t)b * MSL * NKV + kv) * 32;
    // element (pos, d4): src[pos*256 + d4]

    auto issue_tile = [&](int tile, int buf) {
        int pos0 = tile * TILE;
        float4* Kd = Kbuf + buf * TILE_F4;
        float4* Vd = Vbuf + buf * TILE_F4;
#pragma unroll
        for (int i = 0; i < 8; ++i) {
            int lin = (i << 8) + tid;          // 0..2047
            int row = lin >> 5, col = lin & 31;
            size_t g = (size_t)(pos0 + row) * 256 + col;
            cp_async16(&Kd[row * KROW_F4 + col], &Ksrc[g]);
            cp_async16(&Vd[row * KROW_F4 + col], &Vsrc[g]);
        }
    };

    issue_tile(0, 0);
    cp_commit();

    float m = -CUDART_INF_F, l = 0.f;
    float2 acc = make_float2(0.f, 0.f);
    const float scale = 0.08838834764831845f;   // 1/sqrt(128)

    for (int tile = 0; tile < NTILES; ++tile) {
        const int buf = tile & 1;
        if (tile + 1 < NTILES) {
            issue_tile(tile + 1, buf ^ 1);
            cp_commit();
            asm volatile("cp.async.wait_group 1;" ::: "memory");
        } else {
            asm volatile("cp.async.wait_group 0;" ::: "memory");
        }
        __syncthreads();

        float4* Kc = Kbuf + buf * TILE_F4;
        float4* Vc = Vbuf + buf * TILE_F4;

        if (tile == NTILES - 1) {
            // overwrite key/value at position 4095 with the new roped token
            if (tid < 32)
                Kc[63 * KROW_F4 + tid] = ((const float4*)g_kn)[b * 256 + kv * 32 + tid];
            else if (tid < 64)
                Vc[63 * KROW_F4 + (tid - 32)] = ((const float4*)g_vn)[b * 256 + kv * 32 + (tid - 32)];
            __syncthreads();
        }

        // -------- scores: thread (h, t) --------
        float4 sa = make_float4(0.f, 0.f, 0.f, 0.f);
#pragma unroll
        for (int d4 = 0; d4 < 32; ++d4) {
            float4 qv = q4[(h << 5) + d4];            // broadcast
            float4 kk = Kc[t * KROW_F4 + d4];         // conflict-free
            sa.x = fmaf(qv.x, kk.x, sa.x);
            sa.y = fmaf(qv.y, kk.y, sa.y);
            sa.z = fmaf(qv.z, kk.z, sa.z);
            sa.w = fmaf(qv.w, kk.w, sa.w);
        }
        float s = (sa.x + sa.y + sa.z + sa.w) * scale;

        // -------- online softmax bookkeeping --------
        float wm = s;
#pragma unroll
        for (int off = 16; off; off >>= 1)
            wm = fmaxf(wm, __shfl_xor_sync(0xffffffffu, wm, off));
        if (lane == 0) red[warp] = wm;
        __syncthreads();
        float m_new = fmaxf(m, fmaxf(red[h * 2], red[h * 2 + 1]));
        float p = __expf(s - m_new);
        p_sh[(h << 6) + t] = p;
        float ws = p;
#pragma unroll
        for (int off = 16; off; off >>= 1)
            ws += __shfl_xor_sync(0xffffffffu, ws, off);
        if (lane == 0) sums[warp] = ws;
        __syncthreads();
        float alpha = __expf(m - m_new);
        l = l * alpha + sums[h * 2] + sums[h * 2 + 1];
        m = m_new;

        // -------- PV: thread (h, j) accumulates dims (2j, 2j+1) --------
        const float2* V2 = (const float2*)Vc;         // row stride 66 float2
        float2 pa = make_float2(0.f, 0.f), pb = make_float2(0.f, 0.f);
#pragma unroll 4
        for (int tt = 0; tt < TILE; tt += 2) {
            float p0 = p_sh[(h << 6) + tt];
            float p1 = p_sh[(h << 6) + tt + 1];
            float2 v0 = V2[tt * 66 + j];
            float2 v1 = V2[(tt + 1) * 66 + j];
            pa.x = fmaf(p0, v0.x, pa.x);
            pa.y = fmaf(p0, v0.y, pa.y);
            pb.x = fmaf(p1, v1.x, pb.x);
            pb.y = fmaf(p1, v1.y, pb.y);
        }
        acc.x = fmaf(acc.x, alpha, pa.x + pb.x);
        acc.y = fmaf(acc.y, alpha, pa.y + pb.y);

        __syncthreads();   // buffer free before its re-issue next iteration
    }

    float inv = 1.f / l;
    float2 o = make_float2(acc.x * inv, acc.y * inv);
    ((float2*)g_ao)[b * (DIM / 2) + (kv * 4 + h) * 64 + j] = o;
}

// =================================================================
// Stage 3: output projection with wo (4096 rows).
// =================================================================
__global__ __launch_bounds__(256)
void o_kernel(const float* __restrict__ wo, float* __restrict__ out)
{
    extern __shared__ float4 xs4[];
    const int warp = threadIdx.x >> 5;
    const int lane = threadIdx.x & 31;
    const int e0   = (blockIdx.x * 8 + warp) * 2;

    const float4* W0 = (const float4*)(wo + (size_t)e0 * DIM);
    const float4* W1 = (const float4*)(wo + (size_t)(e0 + 1) * DIM);

    float a0[16], a1[16];
    gemv2_16b((const float4*)g_ao, W0, W1, xs4, a0, a1);

    if (lane < 16) {
        int b = lane;
        out[b * DIM + e0]     = a0[b];
        out[b * DIM + e0 + 1] = a1[b];
    }
}

// =================================================================
// Launch
// =================================================================
#define GEMV_SMEM 65536
#define ATTN_SMEM (4 * TILE_F4 * 16 + 128 * 16 + 256 * 4 + 8 * 4 + 8 * 4)  // 138304 B

extern "C" void kernel_launch(void* const* d_in, const int* in_sizes, int n_in,
                              void* d_out, int out_size)
{
    const float* x  = (const float*)d_in[0];
    const float* wq = (const float*)d_in[1];
    const float* wk = (const float*)d_in[2];
    const float* wv = (const float*)d_in[3];
    const float* wo = (const float*)d_in[4];
    const float* ck = (const float*)d_in[5];
    const float* cv = (const float*)d_in[6];
    const float* fc = (const float*)d_in[7];
    const float* fs = (const float*)d_in[8];
    float* out = (float*)d_out;

    cudaFuncSetAttribute(qkv_kernel,  cudaFuncAttributeMaxDynamicSharedMemorySize, GEMV_SMEM);
    cudaFuncSetAttribute(o_kernel,    cudaFuncAttributeMaxDynamicSharedMemorySize, GEMV_SMEM);
    cudaFuncSetAttribute(attn_kernel, cudaFuncAttributeMaxDynamicSharedMemorySize, ATTN_SMEM);

    qkv_kernel<<<384, 256, GEMV_SMEM>>>(x, wq, wk, wv, fc, fs);
    attn_kernel<<<128, 256, ATTN_SMEM>>>(ck, cv);
    o_kernel<<<256, 256, GEMV_SMEM>>>(wo, out);
}